// round 12
// baseline (speedup 1.0000x reference)
#include <cuda_runtime.h>
#include <cuda_bf16.h>
#include <math.h>
#include <stdint.h>

#define NN 50000
#define NE 800000
#define EP (NE + NN)   // edges + self loops
#define FD 128

#define HIST_BLOCKS ((NE + 255) / 256)   // 3125
#define PREP_BLOCKS 24
#define GEMM_BX     ((NN + 127) / 128)   // 391

typedef uint32_t u32;

// -------------------- device scratch (no allocs allowed) --------------------
__device__ float g_Q[NN * FD];
__device__ float g_K[NN * FD];
__device__ float g_V[NN * FD];
__device__ int   g_cnt[NN];      // zeroed at load; re-zeroed by aggregate each replay
__device__ int   g_off[NN + 1];
__device__ int   g_cur[NN];
__device__ int   g_scol[EP];
// W transposed (N-major) + bf16-split: [mat][part(hi/lo)][n=128][kpair=64] u32
__device__ u32   g_Wt[3 * 2 * 128 * 64];

// -------------------- bf16 split helpers (RN-even) --------------------
__device__ __forceinline__ u32 f2bf(float x) {
    u32 u = __float_as_uint(x);
    return (u + 0x7FFFu + ((u >> 16) & 1u)) >> 16;
}
__device__ __forceinline__ float bf2f(u32 b) { return __uint_as_float(b << 16); }

__device__ __forceinline__ u32 smem_u32(const void* p) {
    u32 a; asm("{ .reg .u64 t; cvta.to.shared.u64 t, %1; cvt.u32.u64 %0, t; }"
               : "=r"(a) : "l"(p));
    return a;
}

// -------------------- sort chain (secondary stream) --------------------
__global__ void hist_kernel(const int* __restrict__ ei) {
    int e = blockIdx.x * blockDim.x + threadIdx.x;
    if (e < NE) atomicAdd(&g_cnt[ei[e]], 1);   // target = ei[0][e]
}

// exclusive scan over (g_cnt[i] + 1); +1 = implicit self loop
__global__ __launch_bounds__(1024) void scan_kernel() {
    __shared__ int sums[1024];
    const int t = threadIdx.x;
    const int CH = (NN + 1023) / 1024;   // 49
    int start = t * CH;
    int end   = start + CH; if (end > NN) end = NN;

    int s = 0;
    for (int i = start; i < end; i++) s += g_cnt[i] + 1;
    sums[t] = s;
    __syncthreads();
    for (int d = 1; d < 1024; d <<= 1) {
        int v = (t >= d) ? sums[t - d] : 0;
        __syncthreads();
        sums[t] += v;
        __syncthreads();
    }
    int run = sums[t] - s;
    for (int i = start; i < end; i++) {
        g_off[i] = run;
        g_cur[i] = run;
        run += g_cnt[i] + 1;
    }
    if (start < NN && end == NN) g_off[NN] = run;
}

__global__ void scatter_kernel(const int* __restrict__ ei) {
    int e = blockIdx.x * blockDim.x + threadIdx.x;
    if (e >= EP) return;
    int rr, cc;
    if (e < NE) { rr = ei[e]; cc = ei[NE + e]; }
    else        { rr = e - NE; cc = rr; }          // self loop
    int pos = atomicAdd(&g_cur[rr], 1);
    g_scol[pos] = cc;
}

// -------------------- W prep (main stream, before gemm) --------------------
__global__ __launch_bounds__(256) void prep_kernel(
    const float* __restrict__ Wq, const float* __restrict__ Wk,
    const float* __restrict__ Wv)
{
    int gid = blockIdx.x * 256 + threadIdx.x;   // 0..6143
#pragma unroll
    for (int i = 0; i < 4; i++) {
        int P   = gid + i * 6144;            // 0..24575
        int mat = P >> 13;
        int kp  = (P >> 7) & 63;
        int n   = P & 127;                   // n fastest -> coalesced W reads
        const float* W = (mat == 0) ? Wq : ((mat == 1) ? Wk : Wv);
        float w0 = W[(2 * kp) * FD + n];
        float w1 = W[(2 * kp + 1) * FD + n];
        u32 h0 = f2bf(w0), h1 = f2bf(w1);
        u32 l0 = f2bf(w0 - bf2f(h0)), l1 = f2bf(w1 - bf2f(h1));
        g_Wt[((mat * 2 + 0) * 128 + n) * 64 + kp] = h0 | (h1 << 16);
        g_Wt[((mat * 2 + 1) * 128 + n) * 64 + kp] = l0 | (l1 << 16);
    }
}

// -------------------- HMMA GEMM, column-half (128 x 64 tile) --------------
// 8 warps 4(m) x 2(n), warp tile m32 x n32.  Per ks: 8 LDSM.x4 feed 24 MMAs
// (3-term bf16 split).  68-u32 rows == 4 (mod 32): LDSM conflict-free.
#define XH 0
#define XL 8704
#define WH 17408
#define WL 21760
#define SMEM_BYTES (26112 * 4)   // 104448

__device__ __forceinline__ void mma_bf16(float* c, const u32* a, u32 b0, u32 b1) {
    asm volatile(
        "mma.sync.aligned.m16n8k16.row.col.f32.bf16.bf16.f32 "
        "{%0,%1,%2,%3}, {%4,%5,%6,%7}, {%8,%9}, {%0,%1,%2,%3};"
        : "+f"(c[0]), "+f"(c[1]), "+f"(c[2]), "+f"(c[3])
        : "r"(a[0]), "r"(a[1]), "r"(a[2]), "r"(a[3]), "r"(b0), "r"(b1));
}
__device__ __forceinline__ void ldsm4(u32* r, u32 addr) {
    asm volatile("ldmatrix.sync.aligned.m8n8.x4.shared.b16 {%0,%1,%2,%3}, [%4];"
        : "=r"(r[0]), "=r"(r[1]), "=r"(r[2]), "=r"(r[3]) : "r"(addr));
}

__global__ __launch_bounds__(256) void gemm_mma_kernel(
    const float* __restrict__ x,
    const float* __restrict__ bq, const float* __restrict__ bk,
    int nbase)
{
    extern __shared__ u32 sm[];
    const u32 sb   = smem_u32(sm);
    const int t    = threadIdx.x;
    const int warp = t >> 5;
    const int lane = t & 31;
    const int gID  = lane >> 2;
    const int tig  = lane & 3;
    const int row0 = blockIdx.x * 128;

    // ---- stage x tile: split into bf16 hi/lo ----
    {
        int r    = t >> 1;
        int half = t & 1;
        bool rok = (row0 + r) < NN;
        const float4* xr = (const float4*)(x + (size_t)(row0 + r) * FD + half * 64);
        int base = r * 68 + half * 32;
#pragma unroll
        for (int i = 0; i < 16; i++) {
            float4 v = rok ? xr[i] : make_float4(0.f, 0.f, 0.f, 0.f);
            u32 hx = f2bf(v.x), hy = f2bf(v.y), hz = f2bf(v.z), hw = f2bf(v.w);
            u32 lx = f2bf(v.x - bf2f(hx)), ly = f2bf(v.y - bf2f(hy));
            u32 lz = f2bf(v.z - bf2f(hz)), lw = f2bf(v.w - bf2f(hw));
            sm[XH + base + 2 * i]     = hx | (hy << 16);
            sm[XH + base + 2 * i + 1] = hz | (hw << 16);
            sm[XL + base + 2 * i]     = lx | (ly << 16);
            sm[XL + base + 2 * i + 1] = lz | (lw << 16);
        }
    }

    // warp tiling: wm rows wm*32..+31, wn cols (within half) wn*32..+31
    const int wm = warp & 3;
    const int wn = warp >> 2;
    const int aLRow = (lane & 7) + 8 * ((lane >> 3) & 1);
    const u32 aColB = 16u * (lane >> 4);
    const int bLRow = (lane & 7) + 8 * (lane >> 4);
    const u32 bColB = 16u * ((lane >> 3) & 1);

    const u32 aBaseH0 = sb + 4u * (XH + (u32)(wm * 32 + aLRow) * 68u) + aColB;
    const u32 aBaseH1 = aBaseH0 + 4u * 16u * 68u;
    const u32 aBaseL0 = sb + 4u * (XL + (u32)(wm * 32 + aLRow) * 68u) + aColB;
    const u32 aBaseL1 = aBaseL0 + 4u * 16u * 68u;
    const u32 bOffRow = sb + 4u * (u32)(wn * 32 + bLRow) * 68u + bColB;

    for (int mat = 0; mat < 3; mat++) {
        __syncthreads();   // W buffers free; covers X stage on mat 0
        // stage W^T cols [nbase, nbase+64) hi/lo: 2048 uint4, 8 per thread
        {
#pragma unroll
            for (int j = 0; j < 8; j++) {
                int idx  = j * 256 + t;
                int part = idx >> 10;
                int rem  = idx & 1023;
                int n    = rem >> 4;
                int q4   = rem & 15;
                uint4 v = *(const uint4*)(g_Wt +
                    ((size_t)(mat * 2 + part) * 128 + nbase + n) * 64 + q4 * 4);
                *(uint4*)(sm + (part ? WL : WH) + n * 68 + q4 * 4) = v;
            }
        }
        __syncthreads();

        float acc[2][4][4];
#pragma unroll
        for (int i = 0; i < 2; i++)
#pragma unroll
            for (int nt = 0; nt < 4; nt++)
#pragma unroll
                for (int c = 0; c < 4; c++) acc[i][nt][c] = 0.f;

#pragma unroll
        for (int ks = 0; ks < 8; ks++) {
            u32 ah0[4], ah1[4], al0[4], al1[4], bh[2][4], bl[2][4];
            ldsm4(ah0, aBaseH0 + 32u * ks);
            ldsm4(ah1, aBaseH1 + 32u * ks);
            ldsm4(al0, aBaseL0 + 32u * ks);
            ldsm4(al1, aBaseL1 + 32u * ks);
#pragma unroll
            for (int j = 0; j < 2; j++) {
                ldsm4(bh[j], bOffRow + 4u * (WH + 16u * j * 68u) + 32u * ks);
                ldsm4(bl[j], bOffRow + 4u * (WL + 16u * j * 68u) + 32u * ks);
            }
#pragma unroll
            for (int j = 0; j < 2; j++) {
                mma_bf16(acc[0][2 * j],     ah0, bh[j][0], bh[j][1]);
                mma_bf16(acc[0][2 * j + 1], ah0, bh[j][2], bh[j][3]);
                mma_bf16(acc[1][2 * j],     ah1, bh[j][0], bh[j][1]);
                mma_bf16(acc[1][2 * j + 1], ah1, bh[j][2], bh[j][3]);
                mma_bf16(acc[0][2 * j],     al0, bh[j][0], bh[j][1]);
                mma_bf16(acc[0][2 * j + 1], al0, bh[j][2], bh[j][3]);
                mma_bf16(acc[1][2 * j],     al1, bh[j][0], bh[j][1]);
                mma_bf16(acc[1][2 * j + 1], al1, bh[j][2], bh[j][3]);
                mma_bf16(acc[0][2 * j],     ah0, bl[j][0], bl[j][1]);
                mma_bf16(acc[0][2 * j + 1], ah0, bl[j][2], bl[j][3]);
                mma_bf16(acc[1][2 * j],     ah1, bl[j][0], bl[j][1]);
                mma_bf16(acc[1][2 * j + 1], ah1, bl[j][2], bl[j][3]);
            }
        }

        // ---- epilogue: bias + relu + store ----
        const float* B = (mat == 0) ? bq : ((mat == 1) ? bk : nullptr);
        float* C = (mat == 0) ? g_Q : ((mat == 1) ? g_K : g_V);
        const bool dorelu = (mat < 2);
#pragma unroll
        for (int i = 0; i < 2; i++) {
            int r0 = row0 + wm * 32 + i * 16 + gID;
            int r1 = r0 + 8;
#pragma unroll
            for (int nt = 0; nt < 4; nt++) {
                int col = nbase + wn * 32 + nt * 8 + 2 * tig;
                float2 bv = B ? *(const float2*)(B + col) : make_float2(0.f, 0.f);
                float2 o0 = make_float2(acc[i][nt][0] + bv.x, acc[i][nt][1] + bv.y);
                float2 o1 = make_float2(acc[i][nt][2] + bv.x, acc[i][nt][3] + bv.y);
                if (dorelu) {
                    o0.x = fmaxf(o0.x, 0.f); o0.y = fmaxf(o0.y, 0.f);
                    o1.x = fmaxf(o1.x, 0.f); o1.y = fmaxf(o1.y, 0.f);
                }
                if (r0 < NN) *(float2*)(C + (size_t)r0 * FD + col) = o0;
                if (r1 < NN) *(float2*)(C + (size_t)r1 * FD + col) = o1;
            }
        }
    }
}

// -------------------- fused attention + aggregation, head-half ------------
// One warp per node, cols [hbase, hbase+64): lane owns float2 at hbase+lane*2.
// 8 lanes per 16-dim head -> shfl xor 1,2,4 reduces the head dot product.
__global__ __launch_bounds__(256) void aggregate_kernel(
    const float* __restrict__ bias, float* __restrict__ out, int hbase)
{
    const int warp = (blockIdx.x * blockDim.x + threadIdx.x) >> 5;
    const int lane = threadIdx.x & 31;
    if (warp >= NN) return;
    const int n = warp;
    if (hbase == 0 && lane == 0) g_cnt[n] = 0;     // reset for next replay

    const int co = hbase + lane * 2;
    const float2 q = __ldg((const float2*)(g_Q + (size_t)n * FD + co));

    const int beg = g_off[n];
    const int end = g_off[n + 1];

    float m = -INFINITY;
    float s = 0.f;
    float2 acc = make_float2(0.f, 0.f);

    int e = beg;
    for (; e + 4 <= end; e += 4) {
        int c0 = g_scol[e];
        int c1 = g_scol[e + 1];
        int c2 = g_scol[e + 2];
        int c3 = g_scol[e + 3];
        const float2 k0 = __ldg((const float2*)(g_K + (size_t)c0 * FD + co));
        const float2 k1 = __ldg((const float2*)(g_K + (size_t)c1 * FD + co));
        const float2 k2 = __ldg((const float2*)(g_K + (size_t)c2 * FD + co));
        const float2 k3 = __ldg((const float2*)(g_K + (size_t)c3 * FD + co));
        const float2 v0 = __ldg((const float2*)(g_V + (size_t)c0 * FD + co));
        const float2 v1 = __ldg((const float2*)(g_V + (size_t)c1 * FD + co));
        const float2 v2 = __ldg((const float2*)(g_V + (size_t)c2 * FD + co));
        const float2 v3 = __ldg((const float2*)(g_V + (size_t)c3 * FD + co));

        float t0 = q.x * k0.x + q.y * k0.y;
        float t1 = q.x * k1.x + q.y * k1.y;
        float t2 = q.x * k2.x + q.y * k2.y;
        float t3 = q.x * k3.x + q.y * k3.y;
        t0 += __shfl_xor_sync(0xffffffffu, t0, 1);
        t1 += __shfl_xor_sync(0xffffffffu, t1, 1);
        t2 += __shfl_xor_sync(0xffffffffu, t2, 1);
        t3 += __shfl_xor_sync(0xffffffffu, t3, 1);
        t0 += __shfl_xor_sync(0xffffffffu, t0, 2);
        t1 += __shfl_xor_sync(0xffffffffu, t1, 2);
        t2 += __shfl_xor_sync(0xffffffffu, t2, 2);
        t3 += __shfl_xor_sync(0xffffffffu, t3, 2);
        t0 += __shfl_xor_sync(0xffffffffu, t0, 4);
        t1 += __shfl_xor_sync(0xffffffffu, t1, 4);
        t2 += __shfl_xor_sync(0xffffffffu, t2, 4);
        t3 += __shfl_xor_sync(0xffffffffu, t3, 4);

        float nm = fmaxf(fmaxf(m, fmaxf(t0, t1)), fmaxf(t2, t3));
        float f  = __expf(m - nm);
        float w0 = __expf(t0 - nm);
        float w1 = __expf(t1 - nm);
        float w2 = __expf(t2 - nm);
        float w3 = __expf(t3 - nm);
        s = s * f + ((w0 + w1) + (w2 + w3));
        acc.x = acc.x * f + ((w0 * v0.x + w1 * v1.x) + (w2 * v2.x + w3 * v3.x));
        acc.y = acc.y * f + ((w0 * v0.y + w1 * v1.y) + (w2 * v2.y + w3 * v3.y));
        m = nm;
    }
    for (; e < end; e++) {
        int c0 = g_scol[e];
        const float2 k0 = __ldg((const float2*)(g_K + (size_t)c0 * FD + co));
        const float2 v0 = __ldg((const float2*)(g_V + (size_t)c0 * FD + co));
        float t0 = q.x * k0.x + q.y * k0.y;
        t0 += __shfl_xor_sync(0xffffffffu, t0, 1);
        t0 += __shfl_xor_sync(0xffffffffu, t0, 2);
        t0 += __shfl_xor_sync(0xffffffffu, t0, 4);
        float nm = fmaxf(m, t0);
        float f  = __expf(m - nm);
        float w0 = __expf(t0 - nm);
        s = s * f + w0;
        acc.x = acc.x * f + w0 * v0.x;
        acc.y = acc.y * f + w0 * v0.y;
        m = nm;
    }

    const float inv = 1.f / s;
    const float2 b2 = __ldg((const float2*)(bias + co));
    float2 o = make_float2(acc.x * inv + b2.x, acc.y * inv + b2.y);
    *(float2*)(out + (size_t)n * FD + co) = o;
}

// -------------------- launch: pipelined halves + forked sort chain ----------
extern "C" void kernel_launch(void* const* d_in, const int* in_sizes, int n_in,
                              void* d_out, int out_size)
{
    const float* x  = (const float*)d_in[0];
    const int*   ei = (const int*)d_in[1];
    const float* Wq = (const float*)d_in[2];
    const float* bq = (const float*)d_in[3];
    const float* Wk = (const float*)d_in[4];
    const float* bk = (const float*)d_in[5];
    const float* Wv = (const float*)d_in[6];
    const float* bo = (const float*)d_in[7];
    float* out = (float*)d_out;

    static cudaStream_t s1;
    static cudaEvent_t  eFork, eSort, eG0, eA0;
    static int inited = 0;
    if (!inited) {
        cudaStreamCreateWithFlags(&s1, cudaStreamNonBlocking);
        cudaEventCreateWithFlags(&eFork, cudaEventDisableTiming);
        cudaEventCreateWithFlags(&eSort, cudaEventDisableTiming);
        cudaEventCreateWithFlags(&eG0,   cudaEventDisableTiming);
        cudaEventCreateWithFlags(&eA0,   cudaEventDisableTiming);
        cudaFuncSetAttribute(gemm_mma_kernel,
                             cudaFuncAttributeMaxDynamicSharedMemorySize, SMEM_BYTES);
        inited = 1;
    }

    // fork: sort chain on s1
    cudaEventRecord(eFork, 0);
    cudaStreamWaitEvent(s1, eFork, 0);
    hist_kernel<<<HIST_BLOCKS, 256, 0, s1>>>(ei);
    scan_kernel<<<1, 1024, 0, s1>>>();
    scatter_kernel<<<(EP + 255) / 256, 256, 0, s1>>>(ei);
    cudaEventRecord(eSort, s1);

    // main: prep + first GEMM half (cols 0-63)
    prep_kernel<<<PREP_BLOCKS, 256>>>(Wq, Wk, Wv);
    gemm_mma_kernel<<<GEMM_BX, 256, SMEM_BYTES>>>(x, bq, bk, 0);
    cudaEventRecord(eG0, 0);

    // s1: first aggregate half (needs sort done [in-order] + gemm half 0)
    cudaStreamWaitEvent(s1, eG0, 0);
    aggregate_kernel<<<(NN * 32 + 255) / 256, 256, 0, s1>>>(bo, out, 0);
    cudaEventRecord(eA0, s1);

    // main: second GEMM half (overlaps agg half 0), then second aggregate half
    gemm_mma_kernel<<<GEMM_BX, 256, SMEM_BYTES>>>(x, bq, bk, 64);
    cudaStreamWaitEvent(0, eSort, 0);
    aggregate_kernel<<<(NN * 32 + 255) / 256, 256>>>(bo, out, 64);
    cudaStreamWaitEvent(0, eA0, 0);
}

// round 13
// speedup vs baseline: 1.1578x; 1.1578x over previous
#include <cuda_runtime.h>
#include <cuda_bf16.h>
#include <math.h>
#include <stdint.h>

#define NN 50000
#define NE 800000
#define EP (NE + NN)   // edges + self loops
#define FD 128

#define HIST_BLOCKS ((NE + 255) / 256)   // 3125
#define PREP_BLOCKS 24
#define GEMM_BX     ((NN + 127) / 128)   // 391

typedef uint32_t u32;

// -------------------- device scratch (no allocs allowed) --------------------
__device__ float g_Q[NN * FD];
__device__ float g_K[NN * FD];
__device__ float g_V[NN * FD];
__device__ int   g_cnt[NN];      // zeroed at load; re-zeroed by aggregate each replay
__device__ int   g_off[NN + 1];
__device__ int   g_cur[NN];
__device__ int   g_scol[EP];
// W transposed (N-major) + bf16-split: [mat][part(hi/lo)][n=128][kpair=64] u32
__device__ u32   g_Wt[3 * 2 * 128 * 64];

// -------------------- bf16 split helpers (RN-even) --------------------
__device__ __forceinline__ u32 f2bf(float x) {
    u32 u = __float_as_uint(x);
    return (u + 0x7FFFu + ((u >> 16) & 1u)) >> 16;
}
__device__ __forceinline__ float bf2f(u32 b) { return __uint_as_float(b << 16); }

__device__ __forceinline__ u32 smem_u32(const void* p) {
    u32 a; asm("{ .reg .u64 t; cvta.to.shared.u64 t, %1; cvt.u32.u64 %0, t; }"
               : "=r"(a) : "l"(p));
    return a;
}

// -------------------- sort chain (secondary stream) --------------------
__global__ void hist_kernel(const int* __restrict__ ei) {
    int e = blockIdx.x * blockDim.x + threadIdx.x;
    if (e < NE) atomicAdd(&g_cnt[ei[e]], 1);   // target = ei[0][e]
}

// exclusive scan over (g_cnt[i] + 1); +1 = implicit self loop
__global__ __launch_bounds__(1024) void scan_kernel() {
    __shared__ int sums[1024];
    const int t = threadIdx.x;
    const int CH = (NN + 1023) / 1024;   // 49
    int start = t * CH;
    int end   = start + CH; if (end > NN) end = NN;

    int s = 0;
    for (int i = start; i < end; i++) s += g_cnt[i] + 1;
    sums[t] = s;
    __syncthreads();
    for (int d = 1; d < 1024; d <<= 1) {
        int v = (t >= d) ? sums[t - d] : 0;
        __syncthreads();
        sums[t] += v;
        __syncthreads();
    }
    int run = sums[t] - s;
    for (int i = start; i < end; i++) {
        g_off[i] = run;
        g_cur[i] = run;
        run += g_cnt[i] + 1;
    }
    if (start < NN && end == NN) g_off[NN] = run;
}

__global__ void scatter_kernel(const int* __restrict__ ei) {
    int e = blockIdx.x * blockDim.x + threadIdx.x;
    if (e >= EP) return;
    int rr, cc;
    if (e < NE) { rr = ei[e]; cc = ei[NE + e]; }
    else        { rr = e - NE; cc = rr; }          // self loop
    int pos = atomicAdd(&g_cur[rr], 1);
    g_scol[pos] = cc;
}

// -------------------- W prep (main stream, before gemm) --------------------
__global__ __launch_bounds__(256) void prep_kernel(
    const float* __restrict__ Wq, const float* __restrict__ Wk,
    const float* __restrict__ Wv)
{
    int gid = blockIdx.x * 256 + threadIdx.x;   // 0..6143
#pragma unroll
    for (int i = 0; i < 4; i++) {
        int P   = gid + i * 6144;            // 0..24575
        int mat = P >> 13;
        int kp  = (P >> 7) & 63;
        int n   = P & 127;                   // n fastest -> coalesced W reads
        const float* W = (mat == 0) ? Wq : ((mat == 1) ? Wk : Wv);
        float w0 = W[(2 * kp) * FD + n];
        float w1 = W[(2 * kp + 1) * FD + n];
        u32 h0 = f2bf(w0), h1 = f2bf(w1);
        u32 l0 = f2bf(w0 - bf2f(h0)), l1 = f2bf(w1 - bf2f(h1));
        g_Wt[((mat * 2 + 0) * 128 + n) * 64 + kp] = h0 | (h1 << 16);
        g_Wt[((mat * 2 + 1) * 128 + n) * 64 + kp] = l0 | (l1 << 16);
    }
}

// -------------------- HMMA GEMM: fused 3-term mainloop --------------------
// 128x128x128 per block, 8 warps 4(m)x2(n), warp tile m32 x n64.
// Per ks: 12 LDSM.x4 feed 48 MMAs (3-term bf16 split).
// 68-u32 rows == 4 (mod 32): LDSM 8-row tiles conflict-free.
#define XH 0
#define XL 8704
#define WH 17408
#define WL 26112
#define SMEM_BYTES (34816 * 4)   // 139264

__device__ __forceinline__ void mma_bf16(float* c, const u32* a, u32 b0, u32 b1) {
    asm volatile(
        "mma.sync.aligned.m16n8k16.row.col.f32.bf16.bf16.f32 "
        "{%0,%1,%2,%3}, {%4,%5,%6,%7}, {%8,%9}, {%0,%1,%2,%3};"
        : "+f"(c[0]), "+f"(c[1]), "+f"(c[2]), "+f"(c[3])
        : "r"(a[0]), "r"(a[1]), "r"(a[2]), "r"(a[3]), "r"(b0), "r"(b1));
}
__device__ __forceinline__ void ldsm4(u32* r, u32 addr) {
    asm volatile("ldmatrix.sync.aligned.m8n8.x4.shared.b16 {%0,%1,%2,%3}, [%4];"
        : "=r"(r[0]), "=r"(r[1]), "=r"(r[2]), "=r"(r[3]) : "r"(addr));
}

__global__ __launch_bounds__(256) void gemm_mma_kernel(
    const float* __restrict__ x,
    const float* __restrict__ bq, const float* __restrict__ bk)
{
    extern __shared__ u32 sm[];
    const u32 sb   = smem_u32(sm);
    const int t    = threadIdx.x;
    const int warp = t >> 5;
    const int lane = t & 31;
    const int gID  = lane >> 2;
    const int tig  = lane & 3;
    const int row0 = blockIdx.x * 128;

    // ---- stage x tile: split into bf16 hi/lo ----
    {
        int r    = t >> 1;
        int half = t & 1;
        bool rok = (row0 + r) < NN;
        const float4* xr = (const float4*)(x + (size_t)(row0 + r) * FD + half * 64);
        int base = r * 68 + half * 32;
#pragma unroll
        for (int i = 0; i < 16; i++) {
            float4 v = rok ? xr[i] : make_float4(0.f, 0.f, 0.f, 0.f);
            u32 hx = f2bf(v.x), hy = f2bf(v.y), hz = f2bf(v.z), hw = f2bf(v.w);
            u32 lx = f2bf(v.x - bf2f(hx)), ly = f2bf(v.y - bf2f(hy));
            u32 lz = f2bf(v.z - bf2f(hz)), lw = f2bf(v.w - bf2f(hw));
            sm[XH + base + 2 * i]     = hx | (hy << 16);
            sm[XH + base + 2 * i + 1] = hz | (hw << 16);
            sm[XL + base + 2 * i]     = lx | (ly << 16);
            sm[XL + base + 2 * i + 1] = lz | (lw << 16);
        }
    }

    // warp tiling: wm in [0,4) rows wm*32..+31, wn in [0,2) cols wn*64..+63
    const int wm = warp & 3;
    const int wn = warp >> 2;
    const int aLRow = (lane & 7) + 8 * ((lane >> 3) & 1);
    const u32 aColB = 16u * (lane >> 4);
    const int bLRow = (lane & 7) + 8 * (lane >> 4);
    const u32 bColB = 16u * ((lane >> 3) & 1);

    const u32 aBaseH0 = sb + 4u * (XH + (u32)(wm * 32 + aLRow) * 68u) + aColB;
    const u32 aBaseH1 = aBaseH0 + 4u * 16u * 68u;
    const u32 aBaseL0 = sb + 4u * (XL + (u32)(wm * 32 + aLRow) * 68u) + aColB;
    const u32 aBaseL1 = aBaseL0 + 4u * 16u * 68u;
    const u32 bOffRow = sb + 4u * (u32)(wn * 64 + bLRow) * 68u + bColB;

    for (int mat = 0; mat < 3; mat++) {
        __syncthreads();   // W buffers free (prev mainloop done); covers X stage on mat 0
        {
            int part = t >> 7;
            int n    = t & 127;
            const uint4* src = (const uint4*)(g_Wt + ((mat * 2 + part) * 128 + n) * 64);
            u32* dst = sm + (part ? WL : WH) + n * 68;
#pragma unroll
            for (int j = 0; j < 16; j++)
                *(uint4*)(dst + 4 * j) = src[j];
        }
        __syncthreads();

        float acc[2][8][4];
#pragma unroll
        for (int i = 0; i < 2; i++)
#pragma unroll
            for (int nt = 0; nt < 8; nt++)
#pragma unroll
                for (int c = 0; c < 4; c++) acc[i][nt][c] = 0.f;

#pragma unroll
        for (int ks = 0; ks < 8; ks++) {
            u32 ah0[4], ah1[4], al0[4], al1[4], bh[4][4], bl[4][4];
            ldsm4(ah0, aBaseH0 + 32u * ks);
            ldsm4(ah1, aBaseH1 + 32u * ks);
            ldsm4(al0, aBaseL0 + 32u * ks);
            ldsm4(al1, aBaseL1 + 32u * ks);
#pragma unroll
            for (int j = 0; j < 4; j++) {
                ldsm4(bh[j], bOffRow + 4u * (WH + 16u * j * 68u) + 32u * ks);
                ldsm4(bl[j], bOffRow + 4u * (WL + 16u * j * 68u) + 32u * ks);
            }
#pragma unroll
            for (int j = 0; j < 4; j++) {
                mma_bf16(acc[0][2 * j],     ah0, bh[j][0], bh[j][1]);
                mma_bf16(acc[0][2 * j + 1], ah0, bh[j][2], bh[j][3]);
                mma_bf16(acc[1][2 * j],     ah1, bh[j][0], bh[j][1]);
                mma_bf16(acc[1][2 * j + 1], ah1, bh[j][2], bh[j][3]);
                mma_bf16(acc[0][2 * j],     al0, bh[j][0], bh[j][1]);
                mma_bf16(acc[0][2 * j + 1], al0, bh[j][2], bh[j][3]);
                mma_bf16(acc[1][2 * j],     al1, bh[j][0], bh[j][1]);
                mma_bf16(acc[1][2 * j + 1], al1, bh[j][2], bh[j][3]);
                mma_bf16(acc[0][2 * j],     ah0, bl[j][0], bl[j][1]);
                mma_bf16(acc[0][2 * j + 1], ah0, bl[j][2], bl[j][3]);
                mma_bf16(acc[1][2 * j],     ah1, bl[j][0], bl[j][1]);
                mma_bf16(acc[1][2 * j + 1], ah1, bl[j][2], bl[j][3]);
            }
        }

        // ---- epilogue: bias + relu + store ----
        const float* B = (mat == 0) ? bq : ((mat == 1) ? bk : nullptr);
        float* C = (mat == 0) ? g_Q : ((mat == 1) ? g_K : g_V);
        const bool dorelu = (mat < 2);
#pragma unroll
        for (int i = 0; i < 2; i++) {
            int r0 = row0 + wm * 32 + i * 16 + gID;
            int r1 = r0 + 8;
#pragma unroll
            for (int nt = 0; nt < 8; nt++) {
                int col = wn * 64 + nt * 8 + 2 * tig;
                float2 bv = B ? *(const float2*)(B + col) : make_float2(0.f, 0.f);
                float2 o0 = make_float2(acc[i][nt][0] + bv.x, acc[i][nt][1] + bv.y);
                float2 o1 = make_float2(acc[i][nt][2] + bv.x, acc[i][nt][3] + bv.y);
                if (dorelu) {
                    o0.x = fmaxf(o0.x, 0.f); o0.y = fmaxf(o0.y, 0.f);
                    o1.x = fmaxf(o1.x, 0.f); o1.y = fmaxf(o1.y, 0.f);
                }
                if (r0 < NN) *(float2*)(C + (size_t)r0 * FD + col) = o0;
                if (r1 < NN) *(float2*)(C + (size_t)r1 * FD + col) = o1;
            }
        }
    }
}

// -------------------- fused attention + aggregation --------------------
// ONE WARP PER BLOCK (one node per block): eliminates the intra-block tail
// (block completion = max of 8 Poisson-degree warps previously).
__global__ __launch_bounds__(32) void aggregate_kernel(
    const float* __restrict__ bias, float* __restrict__ out)
{
    const int n    = blockIdx.x;
    const int lane = threadIdx.x;
    if (lane == 0) g_cnt[n] = 0;     // reset for next replay

    const float4 q = __ldg((const float4*)(g_Q + (size_t)n * FD + lane * 4));

    const int beg = g_off[n];
    const int end = g_off[n + 1];

    float m = -INFINITY;
    float s = 0.f;
    float4 acc = make_float4(0.f, 0.f, 0.f, 0.f);

    int e = beg;
    for (; e + 4 <= end; e += 4) {
        int c0 = g_scol[e];
        int c1 = g_scol[e + 1];
        int c2 = g_scol[e + 2];
        int c3 = g_scol[e + 3];
        const float4 k0 = __ldg((const float4*)(g_K + (size_t)c0 * FD + lane * 4));
        const float4 k1 = __ldg((const float4*)(g_K + (size_t)c1 * FD + lane * 4));
        const float4 k2 = __ldg((const float4*)(g_K + (size_t)c2 * FD + lane * 4));
        const float4 k3 = __ldg((const float4*)(g_K + (size_t)c3 * FD + lane * 4));
        const float4 v0 = __ldg((const float4*)(g_V + (size_t)c0 * FD + lane * 4));
        const float4 v1 = __ldg((const float4*)(g_V + (size_t)c1 * FD + lane * 4));
        const float4 v2 = __ldg((const float4*)(g_V + (size_t)c2 * FD + lane * 4));
        const float4 v3 = __ldg((const float4*)(g_V + (size_t)c3 * FD + lane * 4));

        float t0 = q.x * k0.x + q.y * k0.y + q.z * k0.z + q.w * k0.w;
        float t1 = q.x * k1.x + q.y * k1.y + q.z * k1.z + q.w * k1.w;
        float t2 = q.x * k2.x + q.y * k2.y + q.z * k2.z + q.w * k2.w;
        float t3 = q.x * k3.x + q.y * k3.y + q.z * k3.z + q.w * k3.w;
        t0 += __shfl_xor_sync(0xffffffffu, t0, 1);
        t1 += __shfl_xor_sync(0xffffffffu, t1, 1);
        t2 += __shfl_xor_sync(0xffffffffu, t2, 1);
        t3 += __shfl_xor_sync(0xffffffffu, t3, 1);
        t0 += __shfl_xor_sync(0xffffffffu, t0, 2);
        t1 += __shfl_xor_sync(0xffffffffu, t1, 2);
        t2 += __shfl_xor_sync(0xffffffffu, t2, 2);
        t3 += __shfl_xor_sync(0xffffffffu, t3, 2);

        float nm = fmaxf(fmaxf(m, fmaxf(t0, t1)), fmaxf(t2, t3));
        float f  = __expf(m - nm);
        float w0 = __expf(t0 - nm);
        float w1 = __expf(t1 - nm);
        float w2 = __expf(t2 - nm);
        float w3 = __expf(t3 - nm);
        s = s * f + ((w0 + w1) + (w2 + w3));
        acc.x = acc.x * f + ((w0 * v0.x + w1 * v1.x) + (w2 * v2.x + w3 * v3.x));
        acc.y = acc.y * f + ((w0 * v0.y + w1 * v1.y) + (w2 * v2.y + w3 * v3.y));
        acc.z = acc.z * f + ((w0 * v0.z + w1 * v1.z) + (w2 * v2.z + w3 * v3.z));
        acc.w = acc.w * f + ((w0 * v0.w + w1 * v1.w) + (w2 * v2.w + w3 * v3.w));
        m = nm;
    }
    for (; e < end; e++) {
        int c0 = g_scol[e];
        const float4 k0 = __ldg((const float4*)(g_K + (size_t)c0 * FD + lane * 4));
        const float4 v0 = __ldg((const float4*)(g_V + (size_t)c0 * FD + lane * 4));
        float t0 = q.x * k0.x + q.y * k0.y + q.z * k0.z + q.w * k0.w;
        t0 += __shfl_xor_sync(0xffffffffu, t0, 1);
        t0 += __shfl_xor_sync(0xffffffffu, t0, 2);
        float nm = fmaxf(m, t0);
        float f  = __expf(m - nm);
        float w0 = __expf(t0 - nm);
        s = s * f + w0;
        acc.x = acc.x * f + w0 * v0.x;
        acc.y = acc.y * f + w0 * v0.y;
        acc.z = acc.z * f + w0 * v0.z;
        acc.w = acc.w * f + w0 * v0.w;
        m = nm;
    }

    const float inv = 1.f / s;
    const float4 b4 = __ldg((const float4*)(bias + lane * 4));
    float4 o = make_float4(acc.x * inv + b4.x, acc.y * inv + b4.y,
                           acc.z * inv + b4.z, acc.w * inv + b4.w);
    *(float4*)(out + (size_t)n * FD + lane * 4) = o;
}

// -------------------- launch: fork sort chain alongside GEMM chain ----------
extern "C" void kernel_launch(void* const* d_in, const int* in_sizes, int n_in,
                              void* d_out, int out_size)
{
    const float* x  = (const float*)d_in[0];
    const int*   ei = (const int*)d_in[1];
    const float* Wq = (const float*)d_in[2];
    const float* bq = (const float*)d_in[3];
    const float* Wk = (const float*)d_in[4];
    const float* bk = (const float*)d_in[5];
    const float* Wv = (const float*)d_in[6];
    const float* bo = (const float*)d_in[7];
    float* out = (float*)d_out;

    static cudaStream_t s1;
    static cudaEvent_t  eFork, eJoin;
    static int inited = 0;
    if (!inited) {
        cudaStreamCreateWithFlags(&s1, cudaStreamNonBlocking);
        cudaEventCreateWithFlags(&eFork, cudaEventDisableTiming);
        cudaEventCreateWithFlags(&eJoin, cudaEventDisableTiming);
        cudaFuncSetAttribute(gemm_mma_kernel,
                             cudaFuncAttributeMaxDynamicSharedMemorySize, SMEM_BYTES);
        inited = 1;
    }

    // fork: sort chain on s1
    cudaEventRecord(eFork, 0);
    cudaStreamWaitEvent(s1, eFork, 0);
    hist_kernel<<<HIST_BLOCKS, 256, 0, s1>>>(ei);
    scan_kernel<<<1, 1024, 0, s1>>>();
    scatter_kernel<<<(EP + 255) / 256, 256, 0, s1>>>(ei);
    cudaEventRecord(eJoin, s1);

    // main stream: GEMM chain (overlaps the sort chain)
    prep_kernel<<<PREP_BLOCKS, 256>>>(Wq, Wk, Wv);
    gemm_mma_kernel<<<GEMM_BX, 256, SMEM_BYTES>>>(x, bq, bk);

    // join, then aggregate (one warp per block -> no intra-block tail)
    cudaStreamWaitEvent(0, eJoin, 0);
    aggregate_kernel<<<NN, 32>>>(bo, out);
}